// round 12
// baseline (speedup 1.0000x reference)
#include <cuda_runtime.h>
#include <cuda_bf16.h>
#include <cstdint>

// Problem dims
#define BSZ 2
#define SLEN 2048
#define HDIM 512
#define NDIM 64
#define TTOT 4096   // BSZ*SLEN

// ---------------- scratch (device globals; no allocation allowed) ----------
__device__ __align__(16) float g_Ainv[NDIM * NDIM];
__device__ __align__(16) float g_p[TTOT * NDIM];      // p = x @ B_w^T
__device__ __align__(16) float g_hs[TTOT * NDIM];     // scan states
__device__ __align__(16) __nv_bfloat16 g_xh[TTOT * HDIM];   // x hi split
__device__ __align__(16) __nv_bfloat16 g_xl[TTOT * HDIM];   // x lo split
__device__ __align__(16) __nv_bfloat16 g_wh[HDIM * HDIM];   // Dw hi split
__device__ __align__(16) __nv_bfloat16 g_wl[HDIM * HDIM];   // Dw lo split

__device__ __forceinline__ float fast_exp2(float x) {
    float y;
    asm("ex2.approx.ftz.f32 %0, %1;" : "=f"(y) : "f"(x));
    return y;
}

__device__ __forceinline__ uint32_t smem_u32(const void* p) {
    return (uint32_t)__cvta_generic_to_shared(p);
}

__device__ __forceinline__ void ldsm4(uint32_t* r, uint32_t a) {
    asm volatile("ldmatrix.sync.aligned.m8n8.x4.shared.b16 {%0,%1,%2,%3}, [%4];"
                 : "=r"(r[0]), "=r"(r[1]), "=r"(r[2]), "=r"(r[3]) : "r"(a));
}
__device__ __forceinline__ void ldsm2(uint32_t* r, uint32_t a) {
    asm volatile("ldmatrix.sync.aligned.m8n8.x2.shared.b16 {%0,%1}, [%2];"
                 : "=r"(r[0]), "=r"(r[1]) : "r"(a));
}
__device__ __forceinline__ void mma16816(float* d, const uint32_t* a, const uint32_t* b) {
    asm volatile(
        "mma.sync.aligned.m16n8k16.row.col.f32.bf16.bf16.f32 "
        "{%0,%1,%2,%3}, {%4,%5,%6,%7}, {%8,%9}, {%0,%1,%2,%3};"
        : "+f"(d[0]), "+f"(d[1]), "+f"(d[2]), "+f"(d[3])
        : "r"(a[0]), "r"(a[1]), "r"(a[2]), "r"(a[3]), "r"(b[0]), "r"(b[1]));
}

// ===========================================================================
// kernel_conv_x / kernel_conv_w: fp32 -> (hi, lo) bf16 splits.
// ===========================================================================
__global__ void kernel_conv_x(const float* __restrict__ x) {
    int i = (blockIdx.x * 256 + threadIdx.x) * 4;
    float4 v = *(const float4*)(x + i);
    __nv_bfloat16 h0 = __float2bfloat16(v.x);
    __nv_bfloat16 h1 = __float2bfloat16(v.y);
    __nv_bfloat16 h2 = __float2bfloat16(v.z);
    __nv_bfloat16 h3 = __float2bfloat16(v.w);
    __nv_bfloat16 l0 = __float2bfloat16(v.x - __bfloat162float(h0));
    __nv_bfloat16 l1 = __float2bfloat16(v.y - __bfloat162float(h1));
    __nv_bfloat16 l2 = __float2bfloat16(v.z - __bfloat162float(h2));
    __nv_bfloat16 l3 = __float2bfloat16(v.w - __bfloat162float(h3));
    *(__nv_bfloat162*)&g_xh[i + 0] = __halves2bfloat162(h0, h1);
    *(__nv_bfloat162*)&g_xh[i + 2] = __halves2bfloat162(h2, h3);
    *(__nv_bfloat162*)&g_xl[i + 0] = __halves2bfloat162(l0, l1);
    *(__nv_bfloat162*)&g_xl[i + 2] = __halves2bfloat162(l2, l3);
}
__global__ void kernel_conv_w(const float* __restrict__ w) {
    int i = (blockIdx.x * 256 + threadIdx.x) * 4;
    float4 v = *(const float4*)(w + i);
    __nv_bfloat16 h0 = __float2bfloat16(v.x);
    __nv_bfloat16 h1 = __float2bfloat16(v.y);
    __nv_bfloat16 h2 = __float2bfloat16(v.z);
    __nv_bfloat16 h3 = __float2bfloat16(v.w);
    __nv_bfloat16 l0 = __float2bfloat16(v.x - __bfloat162float(h0));
    __nv_bfloat16 l1 = __float2bfloat16(v.y - __bfloat162float(h1));
    __nv_bfloat16 l2 = __float2bfloat16(v.z - __bfloat162float(h2));
    __nv_bfloat16 l3 = __float2bfloat16(v.w - __bfloat162float(h3));
    *(__nv_bfloat162*)&g_wh[i + 0] = __halves2bfloat162(h0, h1);
    *(__nv_bfloat162*)&g_wh[i + 2] = __halves2bfloat162(h2, h3);
    *(__nv_bfloat162*)&g_wl[i + 0] = __halves2bfloat162(l0, l1);
    *(__nv_bfloat162*)&g_wl[i + 2] = __halves2bfloat162(l2, l3);
}

// ===========================================================================
// kernel_y1_mma: Y = x @ Dw^T + (Cb+Db), bf16 tensor-core 2-way split.
// ===========================================================================
#define Y1_TS (128 * 40)
#define Y1_SMEM_BYTES (8 * Y1_TS * 2)

__global__ __launch_bounds__(256, 1)
void kernel_y1_mma(const float* __restrict__ Cb, const float* __restrict__ Db,
                   float* __restrict__ Y) {
    extern __shared__ __nv_bfloat16 smem[];
    __nv_bfloat16* sAh = smem;
    __nv_bfloat16* sAl = smem + 2 * Y1_TS;
    __nv_bfloat16* sBh = smem + 4 * Y1_TS;
    __nv_bfloat16* sBl = smem + 6 * Y1_TS;

    const int tid = threadIdx.x;
    const int m0 = blockIdx.y * 128;
    const int n0 = blockIdx.x * 128;

    const int lrow = tid >> 2;
    const int lch  = (tid & 3) * 8;

    const int lane = tid & 31;
    const int w = tid >> 5;
    const int wm = w & 1;
    const int wn = w >> 1;
    const int a_row = wm * 64 + (lane & 15);
    const int a_col = (lane >> 4) * 8;
    const int b_row = wn * 32 + (lane & 7);
    const int b_col = ((lane >> 3) & 1) * 8;

    float acc[4][4][4] = {};

    uint4 pAh0, pAh1, pAl0, pAl1, pBh0, pBh1, pBl0, pBl1;
    auto fetch = [&](int kt) {
        const int kk = kt * 32 + lch;
        pAh0 = *(const uint4*)&g_xh[(m0 + lrow) * 512 + kk];
        pAh1 = *(const uint4*)&g_xh[(m0 + lrow + 64) * 512 + kk];
        pAl0 = *(const uint4*)&g_xl[(m0 + lrow) * 512 + kk];
        pAl1 = *(const uint4*)&g_xl[(m0 + lrow + 64) * 512 + kk];
        pBh0 = *(const uint4*)&g_wh[(n0 + lrow) * 512 + kk];
        pBh1 = *(const uint4*)&g_wh[(n0 + lrow + 64) * 512 + kk];
        pBl0 = *(const uint4*)&g_wl[(n0 + lrow) * 512 + kk];
        pBl1 = *(const uint4*)&g_wl[(n0 + lrow + 64) * 512 + kk];
    };
    auto stash = [&](int b) {
        const int o0 = b * Y1_TS + lrow * 40 + lch;
        const int o1 = b * Y1_TS + (lrow + 64) * 40 + lch;
        *(uint4*)&sAh[o0] = pAh0;  *(uint4*)&sAh[o1] = pAh1;
        *(uint4*)&sAl[o0] = pAl0;  *(uint4*)&sAl[o1] = pAl1;
        *(uint4*)&sBh[o0] = pBh0;  *(uint4*)&sBh[o1] = pBh1;
        *(uint4*)&sBl[o0] = pBl0;  *(uint4*)&sBl[o1] = pBl1;
    };

    fetch(0);
    stash(0);
    __syncthreads();

    int buf = 0;
    for (int kt = 0; kt < 16; ++kt) {
        if (kt + 1 < 16) fetch(kt + 1);
        const __nv_bfloat16* bAh = sAh + buf * Y1_TS;
        const __nv_bfloat16* bAl = sAl + buf * Y1_TS;
        const __nv_bfloat16* bBh = sBh + buf * Y1_TS;
        const __nv_bfloat16* bBl = sBl + buf * Y1_TS;
        #pragma unroll
        for (int k16 = 0; k16 < 2; ++k16) {
            uint32_t ah[4][4], al[4][4], bh[4][2], bl[4][2];
            #pragma unroll
            for (int mi = 0; mi < 4; ++mi) {
                ldsm4(ah[mi], smem_u32(bAh + (a_row + mi * 16) * 40 + a_col + k16 * 16));
                ldsm4(al[mi], smem_u32(bAl + (a_row + mi * 16) * 40 + a_col + k16 * 16));
            }
            #pragma unroll
            for (int ni = 0; ni < 4; ++ni) {
                ldsm2(bh[ni], smem_u32(bBh + (b_row + ni * 8) * 40 + b_col + k16 * 16));
                ldsm2(bl[ni], smem_u32(bBl + (b_row + ni * 8) * 40 + b_col + k16 * 16));
            }
            #pragma unroll
            for (int mi = 0; mi < 4; ++mi) {
                #pragma unroll
                for (int ni = 0; ni < 4; ++ni) {
                    mma16816(acc[mi][ni], ah[mi], bh[ni]);
                    mma16816(acc[mi][ni], ah[mi], bl[ni]);
                    mma16816(acc[mi][ni], al[mi], bh[ni]);
                }
            }
        }
        if (kt + 1 < 16) {
            stash(buf ^ 1);
            __syncthreads();
            buf ^= 1;
        }
    }

    #pragma unroll
    for (int ni = 0; ni < 4; ++ni) {
        const int gn = n0 + wn * 32 + ni * 8 + (lane & 3) * 2;
        float2 cb = *(const float2*)(Cb + gn);
        float2 db = *(const float2*)(Db + gn);
        const float bx = cb.x + db.x, by = cb.y + db.y;
        #pragma unroll
        for (int mi = 0; mi < 4; ++mi) {
            const int gm = m0 + wm * 64 + mi * 16 + (lane >> 2);
            float2 o0 = {acc[mi][ni][0] + bx, acc[mi][ni][1] + by};
            float2 o1 = {acc[mi][ni][2] + bx, acc[mi][ni][3] + by};
            *(float2*)(Y + gm * 512 + gn) = o0;
            *(float2*)(Y + (gm + 8) * 512 + gn) = o1;
        }
    }
}

// ===========================================================================
// kernel_prep: 8x8 BLOCK-PANEL Gauss-Jordan (no pivoting) + FOUR Newton
// steps. The diag blocks of A (~ -2.4*ones + noise) are rank-1-dominated and
// ill-conditioned, so block GJ alone gives X0 with residual rho0 ~ 0.13
// (measured: 1.7e-2 output error after 1 Newton). Newton squares the
// residual: 1.7e-2 -> 2.9e-4 -> 8e-8 -> fp32 floor. 4 steps = huge margin.
// 512 threads.
// ===========================================================================
#define PREP_SMEM_FLOATS (64*132 + 8*132 + 64 + 512 + 64*68 + 64*68)

__global__ void kernel_prep(const float* __restrict__ A) {
    extern __shared__ float sm[];
    float* M      = sm;               // 64 x 132 augmented [A|I]
    float* sPanel = M + 64 * 132;     // 8 x 132
    float* sDinv  = sPanel + 8 * 132; // 8 x 8
    float* sC     = sDinv + 64;       // 64 x 8
    float* X      = sC + 512;         // 64 x 68
    float* T      = X + 64 * 68;      // 64 x 68
    const int tid = threadIdx.x;

    // load [A | I]
    for (int e = tid; e < 4096; e += 512) {
        int i = e >> 6, j = e & 63;
        M[i * 132 + j] = A[e];
        M[i * 132 + 64 + j] = (i == j) ? 1.0f : 0.0f;
    }
    __syncthreads();

    for (int p = 0; p < 8; ++p) {
        const int p8 = p * 8;
        // ---- phase A: snapshot multiplier block C (all threads, 1 elem each)
        {
            int i = tid >> 3, q = tid & 7;
            sC[tid] = M[i * 132 + p8 + q];
        }
        // warp0 lanes 0-7: invert D = M[P][P] in shuffle registers
        if (tid < 8) {
            float d[16];
            #pragma unroll
            for (int j = 0; j < 8; ++j) d[j] = M[(p8 + tid) * 132 + p8 + j];
            #pragma unroll
            for (int j = 0; j < 8; ++j) d[8 + j] = (tid == j) ? 1.0f : 0.0f;
            #pragma unroll
            for (int k = 0; k < 8; ++k) {
                float pv = __shfl_sync(0xFFu, d[k], k);
                float rcp = 1.0f / pv;
                float f = d[k] * rcp;
                #pragma unroll
                for (int j = 0; j < 16; ++j) {
                    float rkj = __shfl_sync(0xFFu, d[j], k);
                    d[j] = (tid == k) ? rkj * rcp : fmaf(-f, rkj, d[j]);
                }
            }
            #pragma unroll
            for (int j = 0; j < 8; ++j) sDinv[tid * 8 + j] = d[8 + j];
        }
        __syncthreads();
        // ---- phase B: sPanel = Dinv @ M[P][:]
        #pragma unroll
        for (int rep = 0; rep < 2; ++rep) {
            int idx = tid + rep * 512;          // 0..1023
            int r = idx >> 7, j = idx & 127;
            float acc = 0.0f;
            #pragma unroll
            for (int q = 0; q < 8; ++q)
                acc = fmaf(sDinv[r * 8 + q], M[(p8 + q) * 132 + j], acc);
            sPanel[r * 132 + j] = acc;
        }
        __syncthreads();
        // ---- phase C: rank-8 update / panel replacement
        {
            int i = tid >> 3, jq = (tid & 7) * 16;
            if (i >= p8 && i < p8 + 8) {
                int r = i - p8;
                #pragma unroll
                for (int c4 = 0; c4 < 4; ++c4)
                    *(float4*)&M[i * 132 + jq + c4 * 4] =
                        *(const float4*)&sPanel[r * 132 + jq + c4 * 4];
            } else {
                float c[8];
                #pragma unroll
                for (int q = 0; q < 8; ++q) c[q] = sC[i * 8 + q];
                #pragma unroll
                for (int c4 = 0; c4 < 4; ++c4) {
                    float4 v = *(const float4*)&M[i * 132 + jq + c4 * 4];
                    #pragma unroll
                    for (int q = 0; q < 8; ++q) {
                        float4 pnl = *(const float4*)&sPanel[q * 132 + jq + c4 * 4];
                        v.x = fmaf(-c[q], pnl.x, v.x);
                        v.y = fmaf(-c[q], pnl.y, v.y);
                        v.z = fmaf(-c[q], pnl.z, v.z);
                        v.w = fmaf(-c[q], pnl.w, v.w);
                    }
                    *(float4*)&M[i * 132 + jq + c4 * 4] = v;
                }
            }
        }
        __syncthreads();
    }

    // X = right half (= A^-1 up to no-pivot block-GJ error)
    for (int e = tid; e < 4096; e += 512) {
        int i = e >> 6, j = e & 63;
        X[i * 68 + j] = M[i * 132 + 64 + j];
    }
    __syncthreads();
    // reload A into left half
    for (int e = tid; e < 4096; e += 512) {
        int i = e >> 6, j = e & 63;
        M[i * 132 + j] = A[e];
    }
    __syncthreads();

    // FOUR Newton steps: X <- X (2I - A X)
    for (int it = 0; it < 4; ++it) {
        for (int o = tid; o < 1024; o += 512) {
            int i = o >> 4, j4 = (o & 15) * 4;
            float4 acc;
            acc.x = (i == j4 + 0) ? 2.0f : 0.0f;
            acc.y = (i == j4 + 1) ? 2.0f : 0.0f;
            acc.z = (i == j4 + 2) ? 2.0f : 0.0f;
            acc.w = (i == j4 + 3) ? 2.0f : 0.0f;
            #pragma unroll 8
            for (int k2 = 0; k2 < 64; ++k2) {
                float a = M[i * 132 + k2];
                float4 xv = *(const float4*)&X[k2 * 68 + j4];
                acc.x = fmaf(-a, xv.x, acc.x);
                acc.y = fmaf(-a, xv.y, acc.y);
                acc.z = fmaf(-a, xv.z, acc.z);
                acc.w = fmaf(-a, xv.w, acc.w);
            }
            *(float4*)&T[i * 68 + j4] = acc;
        }
        __syncthreads();
        float4 r[2];
        #pragma unroll
        for (int t2 = 0; t2 < 2; ++t2) {
            int o = tid + t2 * 512;
            int i = o >> 4, j4 = (o & 15) * 4;
            float4 acc = {0.f, 0.f, 0.f, 0.f};
            #pragma unroll 8
            for (int k2 = 0; k2 < 64; ++k2) {
                float a = X[i * 68 + k2];
                float4 tv = *(const float4*)&T[k2 * 68 + j4];
                acc.x = fmaf(a, tv.x, acc.x);
                acc.y = fmaf(a, tv.y, acc.y);
                acc.z = fmaf(a, tv.z, acc.z);
                acc.w = fmaf(a, tv.w, acc.w);
            }
            r[t2] = acc;
        }
        __syncthreads();
        #pragma unroll
        for (int t2 = 0; t2 < 2; ++t2) {
            int o = tid + t2 * 512;
            int i = o >> 4, j4 = (o & 15) * 4;
            *(float4*)&X[i * 68 + j4] = r[t2];
        }
        __syncthreads();
    }

    for (int o = tid; o < 1024; o += 512) {
        int i = o >> 4, j4 = (o & 15) * 4;
        *(float4*)&g_Ainv[i * 64 + j4] = *(const float4*)&X[i * 68 + j4];
    }
}

// ===========================================================================
// kernel_p: p = x @ B_w^T   (4096 x 64, K=512), NT GEMM.
// ===========================================================================
__global__ void kernel_p(const float* __restrict__ Xin, const float* __restrict__ Bw) {
    __shared__ float As[2][32][36];
    __shared__ float Bs[2][32][68];
    const int tid = threadIdx.x;
    const int m0 = blockIdx.x * 32;
    const int tx = tid & 15, ty = tid >> 4;

    const int ar  = tid >> 3;
    const int akq = (tid & 7) * 4;
    const int br0 = ar;
    const int br1 = 32 + ar;

    float acc[2][4] = {};
    float4 pa, pb0, pb1;

    pa  = *(const float4*)(Xin + (m0 + ar) * 512 + akq);
    pb0 = *(const float4*)(Bw + br0 * 512 + akq);
    pb1 = *(const float4*)(Bw + br1 * 512 + akq);
    As[0][akq+0][ar] = pa.x;  As[0][akq+1][ar] = pa.y;
    As[0][akq+2][ar] = pa.z;  As[0][akq+3][ar] = pa.w;
    Bs[0][akq+0][br0] = pb0.x; Bs[0][akq+1][br0] = pb0.y;
    Bs[0][akq+2][br0] = pb0.z; Bs[0][akq+3][br0] = pb0.w;
    Bs[0][akq+0][br1] = pb1.x; Bs[0][akq+1][br1] = pb1.y;
    Bs[0][akq+2][br1] = pb1.z; Bs[0][akq+3][br1] = pb1.w;
    __syncthreads();

    int buf = 0;
    for (int kt = 0; kt < 16; ++kt) {
        if (kt + 1 < 16) {
            int kk = (kt + 1) * 32;
            pa  = *(const float4*)(Xin + (m0 + ar) * 512 + kk + akq);
            pb0 = *(const float4*)(Bw + br0 * 512 + kk + akq);
            pb1 = *(const float4*)(Bw + br1 * 512 + kk + akq);
        }
        #pragma unroll
        for (int k = 0; k < 32; ++k) {
            float a0 = As[buf][k][ty * 2 + 0];
            float a1 = As[buf][k][ty * 2 + 1];
            float4 bv = *(const float4*)&Bs[buf][k][tx * 4];
            acc[0][0] = fmaf(a0, bv.x, acc[0][0]);
            acc[0][1] = fmaf(a0, bv.y, acc[0][1]);
            acc[0][2] = fmaf(a0, bv.z, acc[0][2]);
            acc[0][3] = fmaf(a0, bv.w, acc[0][3]);
            acc[1][0] = fmaf(a1, bv.x, acc[1][0]);
            acc[1][1] = fmaf(a1, bv.y, acc[1][1]);
            acc[1][2] = fmaf(a1, bv.z, acc[1][2]);
            acc[1][3] = fmaf(a1, bv.w, acc[1][3]);
        }
        if (kt + 1 < 16) {
            int nb = buf ^ 1;
            As[nb][akq+0][ar] = pa.x;  As[nb][akq+1][ar] = pa.y;
            As[nb][akq+2][ar] = pa.z;  As[nb][akq+3][ar] = pa.w;
            Bs[nb][akq+0][br0] = pb0.x; Bs[nb][akq+1][br0] = pb0.y;
            Bs[nb][akq+2][br0] = pb0.z; Bs[nb][akq+3][br0] = pb0.w;
            Bs[nb][akq+0][br1] = pb1.x; Bs[nb][akq+1][br1] = pb1.y;
            Bs[nb][akq+2][br1] = pb1.z; Bs[nb][akq+3][br1] = pb1.w;
            __syncthreads();
            buf = nb;
        }
    }

    #pragma unroll
    for (int i = 0; i < 2; ++i) {
        float4 o;
        o.x = acc[i][0]; o.y = acc[i][1]; o.z = acc[i][2]; o.w = acc[i][3];
        *(float4*)&g_p[(m0 + ty * 2 + i) * 64 + tx * 4] = o;
    }
}

// ===========================================================================
// kernel_scan: chunked selective scan, register-resident A slices.
// 256 blocks = chunks of 16 steps + 4-step warmup (truncation <= 2e-7).
// ===========================================================================
#define SCAN_STEPS_MAX 20
#define SCAN_SMEM_FLOATS (SCAN_STEPS_MAX*64 + SCAN_STEPS_MAX*64 + 4*SCAN_STEPS_MAX*64 + 64 + 256 + 64)

__global__ void kernel_scan(const float* __restrict__ A, const float* __restrict__ dlt) {
    extern __shared__ float sm[];
    float* sP     = sm;
    float* sV     = sP + SCAN_STEPS_MAX * 64;
    float* sPartV = sV + SCAN_STEPS_MAX * 64;
    float* sDelta = sPartV + 4 * SCAN_STEPS_MAX * 64;
    float* sPart  = sDelta + 64;
    float* sH     = sPart + 256;

    const int tid = threadIdx.x;
    const int g = blockIdx.x;                            // 0..255
    const int lc = g & 127;
    const int warm = lc ? 4 : 0;
    const int t0g = g * 16 - warm;
    const int nsteps = 16 + warm;

    const float LOG2E = 1.4426950408889634f;
    const int n = tid & 63, q = tid >> 6;
    const int mb = q * 16;

    float aCol[16], aRow[16], aInv[16];
    #pragma unroll
    for (int i = 0; i < 16; ++i) {
        aCol[i] = LOG2E * A[(mb + i) * 64 + n];
    }
    #pragma unroll
    for (int i4 = 0; i4 < 4; ++i4) {
        float4 r = *(const float4*)(A + n * 64 + mb + i4 * 4);
        aRow[i4*4+0] = LOG2E * r.x; aRow[i4*4+1] = LOG2E * r.y;
        aRow[i4*4+2] = LOG2E * r.z; aRow[i4*4+3] = LOG2E * r.w;
        float4 iv = *(const float4*)(g_Ainv + n * 64 + mb + i4 * 4);
        aInv[i4*4+0] = iv.x; aInv[i4*4+1] = iv.y;
        aInv[i4*4+2] = iv.z; aInv[i4*4+3] = iv.w;
    }

    for (int e = tid; e < nsteps * 64; e += 256) {
        sP[e] = g_p[t0g * 64 + e];
    }
    if (tid < nsteps) sDelta[tid] = dlt[t0g + tid];
    if (tid < 64) sH[tid] = 0.0f;
    __syncthreads();

    for (int t = 0; t < nsteps; ++t) {
        float acc = 0.0f;
        #pragma unroll
        for (int i4 = 0; i4 < 4; ++i4) {
            float4 pv = *(const float4*)&sP[t * 64 + mb + i4 * 4];
            acc = fmaf(aInv[i4*4+0], pv.x, acc);
            acc = fmaf(aInv[i4*4+1], pv.y, acc);
            acc = fmaf(aInv[i4*4+2], pv.z, acc);
            acc = fmaf(aInv[i4*4+3], pv.w, acc);
        }
        sPartV[q * (SCAN_STEPS_MAX * 64) + t * 64 + n] = acc;
    }
    __syncthreads();
    for (int o = tid; o < nsteps * 64; o += 256) {
        sV[o] = sPartV[o] + sPartV[SCAN_STEPS_MAX*64 + o]
              + sPartV[2*SCAN_STEPS_MAX*64 + o] + sPartV[3*SCAN_STEPS_MAX*64 + o];
    }
    __syncthreads();

    for (int j = 0; j < nsteps; ++j) {
        const float dj = sDelta[j];
        float h[16], v[16];
        #pragma unroll
        for (int i4 = 0; i4 < 4; ++i4) {
            float4 hv = *(const float4*)&sH[mb + i4 * 4];
            h[i4*4+0] = hv.x; h[i4*4+1] = hv.y; h[i4*4+2] = hv.z; h[i4*4+3] = hv.w;
            float4 vv = *(const float4*)&sV[j * 64 + mb + i4 * 4];
            v[i4*4+0] = vv.x; v[i4*4+1] = vv.y; v[i4*4+2] = vv.z; v[i4*4+3] = vv.w;
        }
        float acc = 0.0f;
        #pragma unroll
        for (int i = 0; i < 16; ++i) {
            acc = fmaf(h[i], fast_exp2(dj * aCol[i]), acc);
            acc = fmaf(fast_exp2(dj * aRow[i]), v[i], acc);
        }
        sPart[q * 64 + n] = acc;
        __syncthreads();
        if (tid < 64) {
            float hn = sPart[tid] + sPart[64 + tid] + sPart[128 + tid] + sPart[192 + tid]
                       - sV[j * 64 + tid];
            sH[tid] = hn;
            if (j >= warm) g_hs[(t0g + j) * 64 + tid] = hn;
        }
        __syncthreads();
    }
}

// ===========================================================================
// kernel_y2: Y += hs @ C_w^T.  M=4096, N=512, K=64.
// ===========================================================================
__global__ void kernel_y2(const float* __restrict__ Cw, float* __restrict__ Y) {
    __shared__ float As[2][16][132];
    __shared__ float Bs[2][16][132];
    const int tid = threadIdx.x;
    const int m0 = blockIdx.y * 128;
    const int n0 = blockIdx.x * 128;

    const int r0 = tid >> 2;
    const int r1 = 64 + r0;
    const int kq = (tid & 3) * 4;

    const int w = tid >> 5, lane = tid & 31;
    const int wm = w & 3, wn = w >> 2;
    const int r = lane >> 3, c = lane & 7;
    const int aoff = wm * 32 + r * 8;
    const int boff0 = wn * 64 + c * 4;
    const int boff1 = boff0 + 32;

    float acc[8][8] = {};
    float4 pa0, pa1, pb0, pb1;

    auto fetch = [&](int kt) {
        int kk = kt * 16;
        pa0 = *(const float4*)(g_hs + (m0 + r0) * 64 + kk + kq);
        pa1 = *(const float4*)(g_hs + (m0 + r1) * 64 + kk + kq);
        pb0 = *(const float4*)(Cw + (n0 + r0) * 64 + kk + kq);
        pb1 = *(const float4*)(Cw + (n0 + r1) * 64 + kk + kq);
    };
    auto stash = [&](int b) {
        As[b][kq+0][r0] = pa0.x; As[b][kq+1][r0] = pa0.y;
        As[b][kq+2][r0] = pa0.z; As[b][kq+3][r0] = pa0.w;
        As[b][kq+0][r1] = pa1.x; As[b][kq+1][r1] = pa1.y;
        As[b][kq+2][r1] = pa1.z; As[b][kq+3][r1] = pa1.w;
        Bs[b][kq+0][r0] = pb0.x; Bs[b][kq+1][r0] = pb0.y;
        Bs[b][kq+2][r0] = pb0.z; Bs[b][kq+3][r0] = pb0.w;
        Bs[b][kq+0][r1] = pb1.x; Bs[b][kq+1][r1] = pb1.y;
        Bs[b][kq+2][r1] = pb1.z; Bs[b][kq+3][r1] = pb1.w;
    };

    fetch(0);
    stash(0);
    __syncthreads();

    int buf = 0;
    for (int kt = 0; kt < 4; ++kt) {
        if (kt + 1 < 4) fetch(kt + 1);
        #pragma unroll
        for (int k = 0; k < 16; ++k) {
            float4 a0 = *(const float4*)&As[buf][k][aoff];
            float4 a1 = *(const float4*)&As[buf][k][aoff + 4];
            float4 b0 = *(const float4*)&Bs[buf][k][boff0];
            float4 b1 = *(const float4*)&Bs[buf][k][boff1];
            float av[8] = {a0.x, a0.y, a0.z, a0.w, a1.x, a1.y, a1.z, a1.w};
            float bv[8] = {b0.x, b0.y, b0.z, b0.w, b1.x, b1.y, b1.z, b1.w};
            #pragma unroll
            for (int i = 0; i < 8; ++i) {
                #pragma unroll
                for (int jj = 0; jj < 8; ++jj) {
                    acc[i][jj] = fmaf(av[i], bv[jj], acc[i][jj]);
                }
            }
        }
        if (kt + 1 < 4) {
            stash(buf ^ 1);
            __syncthreads();
            buf ^= 1;
        }
    }

    const int cg0 = n0 + boff0;
    const int cg1 = n0 + boff1;
    #pragma unroll
    for (int i = 0; i < 8; ++i) {
        int gm = m0 + aoff + i;
        float4 y0 = *(const float4*)(Y + gm * 512 + cg0);
        float4 y1 = *(const float4*)(Y + gm * 512 + cg1);
        y0.x += acc[i][0]; y0.y += acc[i][1]; y0.z += acc[i][2]; y0.w += acc[i][3];
        y1.x += acc[i][4]; y1.y += acc[i][5]; y1.z += acc[i][6]; y1.w += acc[i][7];
        *(float4*)(Y + gm * 512 + cg0) = y0;
        *(float4*)(Y + gm * 512 + cg1) = y1;
    }
}

// ===========================================================================
struct LaunchCtx {
    cudaStream_t s1, s2;
    cudaEvent_t e_root, e_prep, e_y1;
    LaunchCtx() {
        cudaStreamCreateWithFlags(&s1, cudaStreamNonBlocking);
        cudaStreamCreateWithFlags(&s2, cudaStreamNonBlocking);
        cudaEventCreateWithFlags(&e_root, cudaEventDisableTiming);
        cudaEventCreateWithFlags(&e_prep, cudaEventDisableTiming);
        cudaEventCreateWithFlags(&e_y1, cudaEventDisableTiming);
    }
};

extern "C" void kernel_launch(void* const* d_in, const int* in_sizes, int n_in,
                              void* d_out, int out_size) {
    const float* x   = (const float*)d_in[0];   // (B,S,H)
    const float* dlt = (const float*)d_in[1];   // (B,S)
    const float* A   = (const float*)d_in[2];   // (N,N)
    const float* Bw  = (const float*)d_in[3];   // (N,H)
    const float* Cw  = (const float*)d_in[4];   // (H,N)
    const float* Cb  = (const float*)d_in[5];   // (H)
    const float* Dw  = (const float*)d_in[6];   // (H,H)
    const float* Db  = (const float*)d_in[7];   // (H)
    float* Y = (float*)d_out;

    static LaunchCtx ctx;

    const int prep_smem = PREP_SMEM_FLOATS * 4;
    const int scan_smem = SCAN_SMEM_FLOATS * 4;
    cudaFuncSetAttribute(kernel_prep, cudaFuncAttributeMaxDynamicSharedMemorySize, prep_smem);
    cudaFuncSetAttribute(kernel_scan, cudaFuncAttributeMaxDynamicSharedMemorySize, scan_smem);
    cudaFuncSetAttribute(kernel_y1_mma, cudaFuncAttributeMaxDynamicSharedMemorySize, Y1_SMEM_BYTES);

    // Fork: s1 (prep), s2 (conv + y1) branch off the main stream.
    cudaEventRecord(ctx.e_root, 0);
    cudaStreamWaitEvent(ctx.s1, ctx.e_root, 0);
    cudaStreamWaitEvent(ctx.s2, ctx.e_root, 0);

    kernel_prep<<<1, 512, prep_smem, ctx.s1>>>(A);
    cudaEventRecord(ctx.e_prep, ctx.s1);

    kernel_conv_x<<<TTOT * HDIM / 1024, 256, 0, ctx.s2>>>(x);
    kernel_conv_w<<<HDIM * HDIM / 1024, 256, 0, ctx.s2>>>(Dw);
    kernel_y1_mma<<<dim3(4, 32), 256, Y1_SMEM_BYTES, ctx.s2>>>(Cb, Db, Y);
    cudaEventRecord(ctx.e_y1, ctx.s2);

    kernel_p<<<128, 256>>>(x, Bw);                 // main stream
    cudaStreamWaitEvent(0, ctx.e_prep, 0);         // scan needs Ainv + p
    kernel_scan<<<256, 256, scan_smem>>>(A, dlt);
    cudaStreamWaitEvent(0, ctx.e_y1, 0);           // y2 accumulates into Y
    kernel_y2<<<dim3(4, 32), 256>>>(Cw, Y);
}

// round 15
// speedup vs baseline: 1.0735x; 1.0735x over previous
#include <cuda_runtime.h>
#include <cuda_bf16.h>
#include <cstdint>

// Problem dims
#define BSZ 2
#define SLEN 2048
#define HDIM 512
#define NDIM 64
#define TTOT 4096   // BSZ*SLEN

// ---------------- scratch (device globals; no allocation allowed) ----------
__device__ __align__(16) float g_Ainv[NDIM * NDIM];
__device__ __align__(16) float g_p[TTOT * NDIM];      // p = x @ B_w^T
__device__ __align__(16) float g_hs[TTOT * NDIM];     // scan states
__device__ __align__(16) __nv_bfloat16 g_xh[TTOT * HDIM];   // x hi split
__device__ __align__(16) __nv_bfloat16 g_xl[TTOT * HDIM];   // x lo split
__device__ __align__(16) __nv_bfloat16 g_wh[HDIM * HDIM];   // Dw hi split
__device__ __align__(16) __nv_bfloat16 g_wl[HDIM * HDIM];   // Dw lo split

__device__ __forceinline__ float fast_exp2(float x) {
    float y;
    asm("ex2.approx.ftz.f32 %0, %1;" : "=f"(y) : "f"(x));
    return y;
}

__device__ __forceinline__ uint32_t smem_u32(const void* p) {
    return (uint32_t)__cvta_generic_to_shared(p);
}

__device__ __forceinline__ void ldsm4(uint32_t* r, uint32_t a) {
    asm volatile("ldmatrix.sync.aligned.m8n8.x4.shared.b16 {%0,%1,%2,%3}, [%4];"
                 : "=r"(r[0]), "=r"(r[1]), "=r"(r[2]), "=r"(r[3]) : "r"(a));
}
__device__ __forceinline__ void ldsm2(uint32_t* r, uint32_t a) {
    asm volatile("ldmatrix.sync.aligned.m8n8.x2.shared.b16 {%0,%1}, [%2];"
                 : "=r"(r[0]), "=r"(r[1]) : "r"(a));
}
__device__ __forceinline__ void mma16816(float* d, const uint32_t* a, const uint32_t* b) {
    asm volatile(
        "mma.sync.aligned.m16n8k16.row.col.f32.bf16.bf16.f32 "
        "{%0,%1,%2,%3}, {%4,%5,%6,%7}, {%8,%9}, {%0,%1,%2,%3};"
        : "+f"(d[0]), "+f"(d[1]), "+f"(d[2]), "+f"(d[3])
        : "r"(a[0]), "r"(a[1]), "r"(a[2]), "r"(a[3]), "r"(b[0]), "r"(b[1]));
}

// ===========================================================================
// kernel_conv: fp32 -> (hi, lo) bf16 splits for BOTH x and Dw in one launch.
// blocks [0, 2048): x (2M elems); blocks [2048, 2304): Dw (256K elems).
// ===========================================================================
__global__ void kernel_conv(const float* __restrict__ x, const float* __restrict__ w) {
    const float* src;
    __nv_bfloat16 *dh, *dl;
    int i;
    if (blockIdx.x < 2048) {
        src = x; dh = g_xh; dl = g_xl;
        i = (blockIdx.x * 256 + threadIdx.x) * 4;
    } else {
        src = w; dh = g_wh; dl = g_wl;
        i = ((blockIdx.x - 2048) * 256 + threadIdx.x) * 4;
    }
    float4 v = *(const float4*)(src + i);
    __nv_bfloat16 h0 = __float2bfloat16(v.x);
    __nv_bfloat16 h1 = __float2bfloat16(v.y);
    __nv_bfloat16 h2 = __float2bfloat16(v.z);
    __nv_bfloat16 h3 = __float2bfloat16(v.w);
    __nv_bfloat16 l0 = __float2bfloat16(v.x - __bfloat162float(h0));
    __nv_bfloat16 l1 = __float2bfloat16(v.y - __bfloat162float(h1));
    __nv_bfloat16 l2 = __float2bfloat16(v.z - __bfloat162float(h2));
    __nv_bfloat16 l3 = __float2bfloat16(v.w - __bfloat162float(h3));
    *(__nv_bfloat162*)&dh[i + 0] = __halves2bfloat162(h0, h1);
    *(__nv_bfloat162*)&dh[i + 2] = __halves2bfloat162(h2, h3);
    *(__nv_bfloat162*)&dl[i + 0] = __halves2bfloat162(l0, l1);
    *(__nv_bfloat162*)&dl[i + 2] = __halves2bfloat162(l2, l3);
}

// ===========================================================================
// kernel_y1_mma: Y = x @ Dw^T + (Cb+Db), bf16 tensor-core 2-way split.
// 512 threads = 16 warps (4x4 warp grid), warp tile 32x32, BM=BN=128, BK=32.
// ===========================================================================
#define Y1_TS (128 * 40)
#define Y1_SMEM_BYTES (8 * Y1_TS * 2)

__global__ __launch_bounds__(512, 1)
void kernel_y1_mma(const float* __restrict__ Cb, const float* __restrict__ Db,
                   float* __restrict__ Y) {
    extern __shared__ __nv_bfloat16 smem[];
    __nv_bfloat16* sAh = smem;
    __nv_bfloat16* sAl = smem + 2 * Y1_TS;
    __nv_bfloat16* sBh = smem + 4 * Y1_TS;
    __nv_bfloat16* sBl = smem + 6 * Y1_TS;

    const int tid = threadIdx.x;
    const int m0 = blockIdx.y * 128;
    const int n0 = blockIdx.x * 128;

    // loader: 512 threads, 1 uint4 per matrix per tile
    const int lrow = tid >> 2;            // 0..127
    const int lch  = (tid & 3) * 8;       // bf16 col offset

    // compute mapping: 16 warps = 4 (M) x 4 (N); warp tile 32x32
    const int lane = tid & 31;
    const int w = tid >> 5;
    const int wm = w & 3;
    const int wn = w >> 2;
    const int a_row = wm * 32 + (lane & 15);
    const int a_col = (lane >> 4) * 8;
    const int b_row = wn * 32 + (lane & 7);
    const int b_col = ((lane >> 3) & 1) * 8;

    float acc[2][4][4] = {};

    uint4 pAh, pAl, pBh, pBl;
    auto fetch = [&](int kt) {
        const int kk = kt * 32 + lch;
        pAh = *(const uint4*)&g_xh[(m0 + lrow) * 512 + kk];
        pAl = *(const uint4*)&g_xl[(m0 + lrow) * 512 + kk];
        pBh = *(const uint4*)&g_wh[(n0 + lrow) * 512 + kk];
        pBl = *(const uint4*)&g_wl[(n0 + lrow) * 512 + kk];
    };
    auto stash = [&](int b) {
        const int o = b * Y1_TS + lrow * 40 + lch;
        *(uint4*)&sAh[o] = pAh;
        *(uint4*)&sAl[o] = pAl;
        *(uint4*)&sBh[o] = pBh;
        *(uint4*)&sBl[o] = pBl;
    };

    fetch(0);
    stash(0);
    __syncthreads();

    int buf = 0;
    for (int kt = 0; kt < 16; ++kt) {
        if (kt + 1 < 16) fetch(kt + 1);
        const __nv_bfloat16* bAh = sAh + buf * Y1_TS;
        const __nv_bfloat16* bAl = sAl + buf * Y1_TS;
        const __nv_bfloat16* bBh = sBh + buf * Y1_TS;
        const __nv_bfloat16* bBl = sBl + buf * Y1_TS;
        #pragma unroll
        for (int k16 = 0; k16 < 2; ++k16) {
            uint32_t ah[2][4], al[2][4], bh[4][2], bl[4][2];
            #pragma unroll
            for (int mi = 0; mi < 2; ++mi) {
                ldsm4(ah[mi], smem_u32(bAh + (a_row + mi * 16) * 40 + a_col + k16 * 16));
                ldsm4(al[mi], smem_u32(bAl + (a_row + mi * 16) * 40 + a_col + k16 * 16));
            }
            #pragma unroll
            for (int ni = 0; ni < 4; ++ni) {
                ldsm2(bh[ni], smem_u32(bBh + (b_row + ni * 8) * 40 + b_col + k16 * 16));
                ldsm2(bl[ni], smem_u32(bBl + (b_row + ni * 8) * 40 + b_col + k16 * 16));
            }
            #pragma unroll
            for (int mi = 0; mi < 2; ++mi) {
                #pragma unroll
                for (int ni = 0; ni < 4; ++ni) {
                    mma16816(acc[mi][ni], ah[mi], bh[ni]);
                    mma16816(acc[mi][ni], ah[mi], bl[ni]);
                    mma16816(acc[mi][ni], al[mi], bh[ni]);
                }
            }
        }
        if (kt + 1 < 16) {
            stash(buf ^ 1);
            __syncthreads();
            buf ^= 1;
        }
    }

    #pragma unroll
    for (int ni = 0; ni < 4; ++ni) {
        const int gn = n0 + wn * 32 + ni * 8 + (lane & 3) * 2;
        float2 cb = *(const float2*)(Cb + gn);
        float2 db = *(const float2*)(Db + gn);
        const float bx = cb.x + db.x, by = cb.y + db.y;
        #pragma unroll
        for (int mi = 0; mi < 2; ++mi) {
            const int gm = m0 + wm * 32 + mi * 16 + (lane >> 2);
            float2 o0 = {acc[mi][ni][0] + bx, acc[mi][ni][1] + by};
            float2 o1 = {acc[mi][ni][2] + bx, acc[mi][ni][3] + by};
            *(float2*)(Y + gm * 512 + gn) = o0;
            *(float2*)(Y + (gm + 8) * 512 + gn) = o1;
        }
    }
}

// ===========================================================================
// kernel_prep: 8x8 block-panel Gauss-Jordan (no pivot) + THREE Newton steps.
// 1024 threads (32 warps). rho chain: 0.13 -> 1.7e-2 -> 2.9e-4 -> 8.4e-8.
// ===========================================================================
#define PREP_SMEM_FLOATS (64*132 + 8*132 + 64 + 512 + 64*68 + 64*68)

__global__ __launch_bounds__(1024, 1)
void kernel_prep(const float* __restrict__ A) {
    extern __shared__ float sm[];
    float* M      = sm;               // 64 x 132 augmented [A|I]
    float* sPanel = M + 64 * 132;     // 8 x 132
    float* sDinv  = sPanel + 8 * 132; // 8 x 8
    float* sC     = sDinv + 64;       // 64 x 8
    float* X      = sC + 512;         // 64 x 68
    float* T      = X + 64 * 68;      // 64 x 68
    const int tid = threadIdx.x;

    // load [A | I]
    for (int e = tid; e < 4096; e += 1024) {
        int i = e >> 6, j = e & 63;
        M[i * 132 + j] = A[e];
        M[i * 132 + 64 + j] = (i == j) ? 1.0f : 0.0f;
    }
    __syncthreads();

    for (int p = 0; p < 8; ++p) {
        const int p8 = p * 8;
        // phase A: snapshot multiplier block C (threads 0..511, 1 elem each)
        if (tid < 512) {
            int i = tid >> 3, q = tid & 7;
            sC[tid] = M[i * 132 + p8 + q];
        }
        // warp0 lanes 0-7: invert D = M[P][P] in shuffle registers
        if (tid < 8) {
            float d[16];
            #pragma unroll
            for (int j = 0; j < 8; ++j) d[j] = M[(p8 + tid) * 132 + p8 + j];
            #pragma unroll
            for (int j = 0; j < 8; ++j) d[8 + j] = (tid == j) ? 1.0f : 0.0f;
            #pragma unroll
            for (int k = 0; k < 8; ++k) {
                float pv = __shfl_sync(0xFFu, d[k], k);
                float rcp = 1.0f / pv;
                float f = d[k] * rcp;
                #pragma unroll
                for (int j = 0; j < 16; ++j) {
                    float rkj = __shfl_sync(0xFFu, d[j], k);
                    d[j] = (tid == k) ? rkj * rcp : fmaf(-f, rkj, d[j]);
                }
            }
            #pragma unroll
            for (int j = 0; j < 8; ++j) sDinv[tid * 8 + j] = d[8 + j];
        }
        __syncthreads();
        // phase B: sPanel = Dinv @ M[P][:]  (exactly 1024 outputs)
        {
            int r = tid >> 7, j = tid & 127;
            float acc = 0.0f;
            #pragma unroll
            for (int q = 0; q < 8; ++q)
                acc = fmaf(sDinv[r * 8 + q], M[(p8 + q) * 132 + j], acc);
            sPanel[r * 132 + j] = acc;
        }
        __syncthreads();
        // phase C: rank-8 update / panel replacement (64 rows x 16 col-groups of 8)
        {
            int i = tid >> 4, jq = (tid & 15) * 8;
            if (i >= p8 && i < p8 + 8) {
                int r = i - p8;
                *(float4*)&M[i * 132 + jq]     = *(const float4*)&sPanel[r * 132 + jq];
                *(float4*)&M[i * 132 + jq + 4] = *(const float4*)&sPanel[r * 132 + jq + 4];
            } else {
                float c[8];
                #pragma unroll
                for (int q = 0; q < 8; ++q) c[q] = sC[i * 8 + q];
                #pragma unroll
                for (int c4 = 0; c4 < 2; ++c4) {
                    float4 v = *(const float4*)&M[i * 132 + jq + c4 * 4];
                    #pragma unroll
                    for (int q = 0; q < 8; ++q) {
                        float4 pnl = *(const float4*)&sPanel[q * 132 + jq + c4 * 4];
                        v.x = fmaf(-c[q], pnl.x, v.x);
                        v.y = fmaf(-c[q], pnl.y, v.y);
                        v.z = fmaf(-c[q], pnl.z, v.z);
                        v.w = fmaf(-c[q], pnl.w, v.w);
                    }
                    *(float4*)&M[i * 132 + jq + c4 * 4] = v;
                }
            }
        }
        __syncthreads();
    }

    // X = right half
    for (int e = tid; e < 4096; e += 1024) {
        int i = e >> 6, j = e & 63;
        X[i * 68 + j] = M[i * 132 + 64 + j];
    }
    __syncthreads();
    // reload A into left half
    for (int e = tid; e < 4096; e += 1024) {
        int i = e >> 6, j = e & 63;
        M[i * 132 + j] = A[e];
    }
    __syncthreads();

    // THREE Newton steps: X <- X (2I - A X); 1024 outputs, 1 per thread.
    for (int it = 0; it < 3; ++it) {
        {
            int i = tid >> 4, j4 = (tid & 15) * 4;
            float4 acc;
            acc.x = (i == j4 + 0) ? 2.0f : 0.0f;
            acc.y = (i == j4 + 1) ? 2.0f : 0.0f;
            acc.z = (i == j4 + 2) ? 2.0f : 0.0f;
            acc.w = (i == j4 + 3) ? 2.0f : 0.0f;
            #pragma unroll 8
            for (int k2 = 0; k2 < 64; ++k2) {
                float a = M[i * 132 + k2];
                float4 xv = *(const float4*)&X[k2 * 68 + j4];
                acc.x = fmaf(-a, xv.x, acc.x);
                acc.y = fmaf(-a, xv.y, acc.y);
                acc.z = fmaf(-a, xv.z, acc.z);
                acc.w = fmaf(-a, xv.w, acc.w);
            }
            *(float4*)&T[i * 68 + j4] = acc;
        }
        __syncthreads();
        float4 r;
        {
            int i = tid >> 4, j4 = (tid & 15) * 4;
            float4 acc = {0.f, 0.f, 0.f, 0.f};
            #pragma unroll 8
            for (int k2 = 0; k2 < 64; ++k2) {
                float a = X[i * 68 + k2];
                float4 tv = *(const float4*)&T[k2 * 68 + j4];
                acc.x = fmaf(a, tv.x, acc.x);
                acc.y = fmaf(a, tv.y, acc.y);
                acc.z = fmaf(a, tv.z, acc.z);
                acc.w = fmaf(a, tv.w, acc.w);
            }
            r = acc;
        }
        __syncthreads();
        {
            int i = tid >> 4, j4 = (tid & 15) * 4;
            *(float4*)&X[i * 68 + j4] = r;
        }
        __syncthreads();
    }

    {
        int i = tid >> 4, j4 = (tid & 15) * 4;
        *(float4*)&g_Ainv[i * 64 + j4] = *(const float4*)&X[i * 68 + j4];
    }
}

// ===========================================================================
// kernel_p: p = x @ B_w^T   (4096 x 64, K=512), NT GEMM.
// ===========================================================================
__global__ void kernel_p(const float* __restrict__ Xin, const float* __restrict__ Bw) {
    __shared__ float As[2][32][36];
    __shared__ float Bs[2][32][68];
    const int tid = threadIdx.x;
    const int m0 = blockIdx.x * 32;
    const int tx = tid & 15, ty = tid >> 4;

    const int ar  = tid >> 3;
    const int akq = (tid & 7) * 4;
    const int br0 = ar;
    const int br1 = 32 + ar;

    float acc[2][4] = {};
    float4 pa, pb0, pb1;

    pa  = *(const float4*)(Xin + (m0 + ar) * 512 + akq);
    pb0 = *(const float4*)(Bw + br0 * 512 + akq);
    pb1 = *(const float4*)(Bw + br1 * 512 + akq);
    As[0][akq+0][ar] = pa.x;  As[0][akq+1][ar] = pa.y;
    As[0][akq+2][ar] = pa.z;  As[0][akq+3][ar] = pa.w;
    Bs[0][akq+0][br0] = pb0.x; Bs[0][akq+1][br0] = pb0.y;
    Bs[0][akq+2][br0] = pb0.z; Bs[0][akq+3][br0] = pb0.w;
    Bs[0][akq+0][br1] = pb1.x; Bs[0][akq+1][br1] = pb1.y;
    Bs[0][akq+2][br1] = pb1.z; Bs[0][akq+3][br1] = pb1.w;
    __syncthreads();

    int buf = 0;
    for (int kt = 0; kt < 16; ++kt) {
        if (kt + 1 < 16) {
            int kk = (kt + 1) * 32;
            pa  = *(const float4*)(Xin + (m0 + ar) * 512 + kk + akq);
            pb0 = *(const float4*)(Bw + br0 * 512 + kk + akq);
            pb1 = *(const float4*)(Bw + br1 * 512 + kk + akq);
        }
        #pragma unroll
        for (int k = 0; k < 32; ++k) {
            float a0 = As[buf][k][ty * 2 + 0];
            float a1 = As[buf][k][ty * 2 + 1];
            float4 bv = *(const float4*)&Bs[buf][k][tx * 4];
            acc[0][0] = fmaf(a0, bv.x, acc[0][0]);
            acc[0][1] = fmaf(a0, bv.y, acc[0][1]);
            acc[0][2] = fmaf(a0, bv.z, acc[0][2]);
            acc[0][3] = fmaf(a0, bv.w, acc[0][3]);
            acc[1][0] = fmaf(a1, bv.x, acc[1][0]);
            acc[1][1] = fmaf(a1, bv.y, acc[1][1]);
            acc[1][2] = fmaf(a1, bv.z, acc[1][2]);
            acc[1][3] = fmaf(a1, bv.w, acc[1][3]);
        }
        if (kt + 1 < 16) {
            int nb = buf ^ 1;
            As[nb][akq+0][ar] = pa.x;  As[nb][akq+1][ar] = pa.y;
            As[nb][akq+2][ar] = pa.z;  As[nb][akq+3][ar] = pa.w;
            Bs[nb][akq+0][br0] = pb0.x; Bs[nb][akq+1][br0] = pb0.y;
            Bs[nb][akq+2][br0] = pb0.z; Bs[nb][akq+3][br0] = pb0.w;
            Bs[nb][akq+0][br1] = pb1.x; Bs[nb][akq+1][br1] = pb1.y;
            Bs[nb][akq+2][br1] = pb1.z; Bs[nb][akq+3][br1] = pb1.w;
            __syncthreads();
            buf = nb;
        }
    }

    #pragma unroll
    for (int i = 0; i < 2; ++i) {
        float4 o;
        o.x = acc[i][0]; o.y = acc[i][1]; o.z = acc[i][2]; o.w = acc[i][3];
        *(float4*)&g_p[(m0 + ty * 2 + i) * 64 + tx * 4] = o;
    }
}

// ===========================================================================
// kernel_scan: chunked selective scan, register-resident A slices.
// 256 blocks = chunks of 16 steps + 4-step warmup (truncation <= 2e-7).
// ===========================================================================
#define SCAN_STEPS_MAX 20
#define SCAN_SMEM_FLOATS (SCAN_STEPS_MAX*64 + SCAN_STEPS_MAX*64 + 4*SCAN_STEPS_MAX*64 + 64 + 256 + 64)

__global__ void kernel_scan(const float* __restrict__ A, const float* __restrict__ dlt) {
    extern __shared__ float sm[];
    float* sP     = sm;
    float* sV     = sP + SCAN_STEPS_MAX * 64;
    float* sPartV = sV + SCAN_STEPS_MAX * 64;
    float* sDelta = sPartV + 4 * SCAN_STEPS_MAX * 64;
    float* sPart  = sDelta + 64;
    float* sH     = sPart + 256;

    const int tid = threadIdx.x;
    const int g = blockIdx.x;                            // 0..255
    const int lc = g & 127;
    const int warm = lc ? 4 : 0;
    const int t0g = g * 16 - warm;
    const int nsteps = 16 + warm;

    const float LOG2E = 1.4426950408889634f;
    const int n = tid & 63, q = tid >> 6;
    const int mb = q * 16;

    float aCol[16], aRow[16], aInv[16];
    #pragma unroll
    for (int i = 0; i < 16; ++i) {
        aCol[i] = LOG2E * A[(mb + i) * 64 + n];
    }
    #pragma unroll
    for (int i4 = 0; i4 < 4; ++i4) {
        float4 r = *(const float4*)(A + n * 64 + mb + i4 * 4);
        aRow[i4*4+0] = LOG2E * r.x; aRow[i4*4+1] = LOG2E * r.y;
        aRow[i4*4+2] = LOG2E * r.z; aRow[i4*4+3] = LOG2E * r.w;
        float4 iv = *(const float4*)(g_Ainv + n * 64 + mb + i4 * 4);
        aInv[i4*4+0] = iv.x; aInv[i4*4+1] = iv.y;
        aInv[i4*4+2] = iv.z; aInv[i4*4+3] = iv.w;
    }

    for (int e = tid; e < nsteps * 64; e += 256) {
        sP[e] = g_p[t0g * 64 + e];
    }
    if (tid < nsteps) sDelta[tid] = dlt[t0g + tid];
    if (tid < 64) sH[tid] = 0.0f;
    __syncthreads();

    for (int t = 0; t < nsteps; ++t) {
        float acc = 0.0f;
        #pragma unroll
        for (int i4 = 0; i4 < 4; ++i4) {
            float4 pv = *(const float4*)&sP[t * 64 + mb + i4 * 4];
            acc = fmaf(aInv[i4*4+0], pv.x, acc);
            acc = fmaf(aInv[i4*4+1], pv.y, acc);
            acc = fmaf(aInv[i4*4+2], pv.z, acc);
            acc = fmaf(aInv[i4*4+3], pv.w, acc);
        }
        sPartV[q * (SCAN_STEPS_MAX * 64) + t * 64 + n] = acc;
    }
    __syncthreads();
    for (int o = tid; o < nsteps * 64; o += 256) {
        sV[o] = sPartV[o] + sPartV[SCAN_STEPS_MAX*64 + o]
              + sPartV[2*SCAN_STEPS_MAX*64 + o] + sPartV[3*SCAN_STEPS_MAX*64 + o];
    }
    __syncthreads();

    for (int j = 0; j < nsteps; ++j) {
        const float dj = sDelta[j];
        float h[16], v[16];
        #pragma unroll
        for (int i4 = 0; i4 < 4; ++i4) {
            float4 hv = *(const float4*)&sH[mb + i4 * 4];
            h[i4*4+0] = hv.x; h[i4*4+1] = hv.y; h[i4*4+2] = hv.z; h[i4*4+3] = hv.w;
            float4 vv = *(const float4*)&sV[j * 64 + mb + i4 * 4];
            v[i4*4+0] = vv.x; v[i4*4+1] = vv.y; v[i4*4+2] = vv.z; v[i4*4+3] = vv.w;
        }
        float acc = 0.0f;
        #pragma unroll
        for (int i = 0; i < 16; ++i) {
            acc = fmaf(h[i], fast_exp2(dj * aCol[i]), acc);
            acc = fmaf(fast_exp2(dj * aRow[i]), v[i], acc);
        }
        sPart[q * 64 + n] = acc;
        __syncthreads();
        if (tid < 64) {
            float hn = sPart[tid] + sPart[64 + tid] + sPart[128 + tid] + sPart[192 + tid]
                       - sV[j * 64 + tid];
            sH[tid] = hn;
            if (j >= warm) g_hs[(t0g + j) * 64 + tid] = hn;
        }
        __syncthreads();
    }
}

// ===========================================================================
// kernel_y2: Y += hs @ C_w^T.  M=4096, N=512, K=64.
// ===========================================================================
__global__ void kernel_y2(const float* __restrict__ Cw, float* __restrict__ Y) {
    __shared__ float As[2][16][132];
    __shared__ float Bs[2][16][132];
    const int tid = threadIdx.x;
    const int m0 = blockIdx.y * 128;
    const int n0 = blockIdx.x * 128;

    const int r0 = tid >> 2;
    const int r1 = 64 + r0;
    const int kq = (tid & 3) * 4;

    const int w = tid >> 5, lane = tid & 31;
    const int wm = w & 3, wn = w >> 2;
    const int r = lane >> 3, c = lane & 7;
    const int aoff = wm * 32 + r * 8;
    const int boff0 = wn * 64 + c * 4;
    const int boff1 = boff0 + 32;

    float acc[8][8] = {};
    float4 pa0, pa1, pb0, pb1;

    auto fetch = [&](int kt) {
        int kk = kt * 16;
        pa0 = *(const float4*)(g_hs + (m0 + r0) * 64 + kk + kq);
        pa1 = *(const float4*)(g_hs + (m0 + r1) * 64 + kk + kq);
        pb0 = *(const float4*)(Cw + (n0 + r0) * 64 + kk + kq);
        pb1 = *(const float4*)(Cw + (n0 + r1) * 64 + kk + kq);
    };
    auto stash = [&](int b) {
        As[b][kq+0][r0] = pa0.x; As[b][kq+1][r0] = pa0.y;
        As[b][kq+2][r0] = pa0.z; As[b][kq+3][r0] = pa0.w;
        As[b][kq+0][r1] = pa1.x; As[b][kq+1][r1] = pa1.y;
        As[b][kq+2][r1] = pa1.z; As[b][kq+3][r1] = pa1.w;
        Bs[b][kq+0][r0] = pb0.x; Bs[b][kq+1][r0] = pb0.y;
        Bs[b][kq+2][r0] = pb0.z; Bs[b][kq+3][r0] = pb0.w;
        Bs[b][kq+0][r1] = pb1.x; Bs[b][kq+1][r1] = pb1.y;
        Bs[b][kq+2][r1] = pb1.z; Bs[b][kq+3][r1] = pb1.w;
    };

    fetch(0);
    stash(0);
    __syncthreads();

    int buf = 0;
    for (int kt = 0; kt < 4; ++kt) {
        if (kt + 1 < 4) fetch(kt + 1);
        #pragma unroll
        for (int k = 0; k < 16; ++k) {
            float4 a0 = *(const float4*)&As[buf][k][aoff];
            float4 a1 = *(const float4*)&As[buf][k][aoff + 4];
            float4 b0 = *(const float4*)&Bs[buf][k][boff0];
            float4 b1 = *(const float4*)&Bs[buf][k][boff1];
            float av[8] = {a0.x, a0.y, a0.z, a0.w, a1.x, a1.y, a1.z, a1.w};
            float bv[8] = {b0.x, b0.y, b0.z, b0.w, b1.x, b1.y, b1.z, b1.w};
            #pragma unroll
            for (int i = 0; i < 8; ++i) {
                #pragma unroll
                for (int jj = 0; jj < 8; ++jj) {
                    acc[i][jj] = fmaf(av[i], bv[jj], acc[i][jj]);
                }
            }
        }
        if (kt + 1 < 4) {
            stash(buf ^ 1);
            __syncthreads();
            buf ^= 1;
        }
    }

    const int cg0 = n0 + boff0;
    const int cg1 = n0 + boff1;
    #pragma unroll
    for (int i = 0; i < 8; ++i) {
        int gm = m0 + aoff + i;
        float4 y0 = *(const float4*)(Y + gm * 512 + cg0);
        float4 y1 = *(const float4*)(Y + gm * 512 + cg1);
        y0.x += acc[i][0]; y0.y += acc[i][1]; y0.z += acc[i][2]; y0.w += acc[i][3];
        y1.x += acc[i][4]; y1.y += acc[i][5]; y1.z += acc[i][6]; y1.w += acc[i][7];
        *(float4*)(Y + gm * 512 + cg0) = y0;
        *(float4*)(Y + gm * 512 + cg1) = y1;
    }
}

// ===========================================================================
struct LaunchCtx {
    cudaStream_t s1, s2;
    cudaEvent_t e_root, e_prep, e_y1;
    LaunchCtx() {
        cudaStreamCreateWithFlags(&s1, cudaStreamNonBlocking);
        cudaStreamCreateWithFlags(&s2, cudaStreamNonBlocking);
        cudaEventCreateWithFlags(&e_root, cudaEventDisableTiming);
        cudaEventCreateWithFlags(&e_prep, cudaEventDisableTiming);
        cudaEventCreateWithFlags(&e_y1, cudaEventDisableTiming);
    }
};

extern "C" void kernel_launch(void* const* d_in, const int* in_sizes, int n_in,
                              void* d_out, int out_size) {
    const float* x   = (const float*)d_in[0];   // (B,S,H)
    const float* dlt = (const float*)d_in[1];   // (B,S)
    const float* A   = (const float*)d_in[2];   // (N,N)
    const float* Bw  = (const float*)d_in[3];   // (N,H)
    const float* Cw  = (const float*)d_in[4];   // (H,N)
    const float* Cb  = (const float*)d_in[5];   // (H)
    const float* Dw  = (const float*)d_in[6];   // (H,H)
    const float* Db  = (const float*)d_in[7];   // (H)
    float* Y = (float*)d_out;

    static LaunchCtx ctx;

    const int prep_smem = PREP_SMEM_FLOATS * 4;
    const int scan_smem = SCAN_SMEM_FLOATS * 4;
    cudaFuncSetAttribute(kernel_prep, cudaFuncAttributeMaxDynamicSharedMemorySize, prep_smem);
    cudaFuncSetAttribute(kernel_scan, cudaFuncAttributeMaxDynamicSharedMemorySize, scan_smem);
    cudaFuncSetAttribute(kernel_y1_mma, cudaFuncAttributeMaxDynamicSharedMemorySize, Y1_SMEM_BYTES);

    // Fork: s2 (conv + y1) and s1 (prep) branch off the main stream.
    cudaEventRecord(ctx.e_root, 0);
    cudaStreamWaitEvent(ctx.s1, ctx.e_root, 0);
    cudaStreamWaitEvent(ctx.s2, ctx.e_root, 0);

    kernel_conv<<<2048 + 256, 256, 0, ctx.s2>>>(x, Dw);
    kernel_y1_mma<<<dim3(4, 32), 512, Y1_SMEM_BYTES, ctx.s2>>>(Cb, Db, Y);
    cudaEventRecord(ctx.e_y1, ctx.s2);

    kernel_prep<<<1, 1024, prep_smem, ctx.s1>>>(A);
    cudaEventRecord(ctx.e_prep, ctx.s1);

    kernel_p<<<128, 256>>>(x, Bw);                 // main stream
    cudaStreamWaitEvent(0, ctx.e_prep, 0);         // scan needs Ainv + p
    kernel_scan<<<256, 256, scan_smem>>>(A, dlt);
    cudaStreamWaitEvent(0, ctx.e_y1, 0);           // y2 accumulates into Y
    kernel_y2<<<dim3(4, 32), 256>>>(Cw, Y);
}

// round 16
// speedup vs baseline: 1.2819x; 1.1941x over previous
#include <cuda_runtime.h>
#include <cuda_bf16.h>
#include <cstdint>

// Problem dims
#define BSZ 2
#define SLEN 2048
#define HDIM 512
#define NDIM 64
#define TTOT 4096   // BSZ*SLEN

// ---------------- scratch (device globals; no allocation allowed) ----------
__device__ __align__(16) float g_Ainv[NDIM * NDIM];
__device__ __align__(16) float g_p[TTOT * NDIM];      // p = x @ B_w^T
__device__ __align__(16) float g_hs[TTOT * NDIM];     // scan states

__device__ __forceinline__ float fast_exp2(float x) {
    float y;
    asm("ex2.approx.ftz.f32 %0, %1;" : "=f"(y) : "f"(x));
    return y;
}

__device__ __forceinline__ uint32_t smem_u32(const void* p) {
    return (uint32_t)__cvta_generic_to_shared(p);
}

__device__ __forceinline__ void ldsm4(uint32_t* r, uint32_t a) {
    asm volatile("ldmatrix.sync.aligned.m8n8.x4.shared.b16 {%0,%1,%2,%3}, [%4];"
                 : "=r"(r[0]), "=r"(r[1]), "=r"(r[2]), "=r"(r[3]) : "r"(a));
}
__device__ __forceinline__ void ldsm2(uint32_t* r, uint32_t a) {
    asm volatile("ldmatrix.sync.aligned.m8n8.x2.shared.b16 {%0,%1}, [%2];"
                 : "=r"(r[0]), "=r"(r[1]) : "r"(a));
}
__device__ __forceinline__ void mma16816(float* d, const uint32_t* a, const uint32_t* b) {
    asm volatile(
        "mma.sync.aligned.m16n8k16.row.col.f32.bf16.bf16.f32 "
        "{%0,%1,%2,%3}, {%4,%5,%6,%7}, {%8,%9}, {%0,%1,%2,%3};"
        : "+f"(d[0]), "+f"(d[1]), "+f"(d[2]), "+f"(d[3])
        : "r"(a[0]), "r"(a[1]), "r"(a[2]), "r"(a[3]), "r"(b[0]), "r"(b[1]));
}

__device__ __forceinline__ uint32_t pack2(__nv_bfloat16 a, __nv_bfloat16 b) {
    __nv_bfloat162 t = __halves2bfloat162(a, b);
    return *(uint32_t*)&t;
}

// split 8 fp32 -> (hi, lo) bf16x8 packed as uint4
__device__ __forceinline__ void split8(const float4& a, const float4& b,
                                       uint4& hi, uint4& lo) {
    float f[8] = {a.x, a.y, a.z, a.w, b.x, b.y, b.z, b.w};
    __nv_bfloat16 h[8];
    __nv_bfloat16 l[8];
    #pragma unroll
    for (int j = 0; j < 8; ++j) {
        h[j] = __float2bfloat16(f[j]);
        l[j] = __float2bfloat16(f[j] - __bfloat162float(h[j]));
    }
    hi.x = pack2(h[0], h[1]); hi.y = pack2(h[2], h[3]);
    hi.z = pack2(h[4], h[5]); hi.w = pack2(h[6], h[7]);
    lo.x = pack2(l[0], l[1]); lo.y = pack2(l[2], l[3]);
    lo.z = pack2(l[4], l[5]); lo.w = pack2(l[6], l[7]);
}

// ===========================================================================
// kernel_y1p: fused conv + y1 + p.
// grid (5, 32), 512 threads = 16 warps (4 M x 4 N), warp tile 32x32.
//  bx in 0..3: Y[m0:m0+128, bx*128:+128] = x @ Dw^T + (Cb+Db)
//  bx == 4  : g_p[m0:m0+128, 0:64] = x @ Bw^T   (only warps wn<2 store)
// Loaders read fp32 x / Dw / Bw and split into hi/lo bf16 in registers.
// 3-product split mma: A_h*B_h + A_h*B_l + A_l*B_h (~2^-16 rel error).
// ===========================================================================
#define Y1_TS (128 * 40)
#define Y1_SMEM_BYTES (8 * Y1_TS * 2)

__global__ __launch_bounds__(512, 1)
void kernel_y1p(const float* __restrict__ Xin, const float* __restrict__ Dw,
                const float* __restrict__ Bw,
                const float* __restrict__ Cb, const float* __restrict__ Db,
                float* __restrict__ Y) {
    extern __shared__ __nv_bfloat16 smem[];
    __nv_bfloat16* sAh = smem;
    __nv_bfloat16* sAl = smem + 2 * Y1_TS;
    __nv_bfloat16* sBh = smem + 4 * Y1_TS;
    __nv_bfloat16* sBl = smem + 6 * Y1_TS;

    const int tid = threadIdx.x;
    const int bx = blockIdx.x;
    const bool is_p = (bx == 4);
    const int m0 = blockIdx.y * 128;
    const int n0 = bx * 128;

    const int lrow = tid >> 2;            // 0..127
    const int lch  = (tid & 3) * 8;       // fp32/bf16 col offset

    const int lane = tid & 31;
    const int w = tid >> 5;
    const int wm = w & 3;
    const int wn = w >> 2;
    const int a_row = wm * 32 + (lane & 15);
    const int a_col = (lane >> 4) * 8;
    const int b_row = wn * 32 + (lane & 7);
    const int b_col = ((lane >> 3) & 1) * 8;

    float acc[2][4][4] = {};

    uint4 pAh, pAl, pBh, pBl;
    auto fetch = [&](int kt) {
        const int kk = kt * 32 + lch;
        float4 a0 = *(const float4*)(Xin + (m0 + lrow) * 512 + kk);
        float4 a1 = *(const float4*)(Xin + (m0 + lrow) * 512 + kk + 4);
        split8(a0, a1, pAh, pAl);
        float4 b0, b1;
        if (!is_p) {
            b0 = *(const float4*)(Dw + (n0 + lrow) * 512 + kk);
            b1 = *(const float4*)(Dw + (n0 + lrow) * 512 + kk + 4);
        } else if (lrow < 64) {
            b0 = *(const float4*)(Bw + lrow * 512 + kk);
            b1 = *(const float4*)(Bw + lrow * 512 + kk + 4);
        } else {
            b0 = make_float4(0.f, 0.f, 0.f, 0.f);
            b1 = b0;
        }
        split8(b0, b1, pBh, pBl);
    };
    auto stash = [&](int b) {
        const int o = b * Y1_TS + lrow * 40 + lch;
        *(uint4*)&sAh[o] = pAh;
        *(uint4*)&sAl[o] = pAl;
        *(uint4*)&sBh[o] = pBh;
        *(uint4*)&sBl[o] = pBl;
    };

    fetch(0);
    stash(0);
    __syncthreads();

    int buf = 0;
    for (int kt = 0; kt < 16; ++kt) {
        if (kt + 1 < 16) fetch(kt + 1);
        const __nv_bfloat16* bAh = sAh + buf * Y1_TS;
        const __nv_bfloat16* bAl = sAl + buf * Y1_TS;
        const __nv_bfloat16* bBh = sBh + buf * Y1_TS;
        const __nv_bfloat16* bBl = sBl + buf * Y1_TS;
        #pragma unroll
        for (int k16 = 0; k16 < 2; ++k16) {
            uint32_t ah[2][4], al[2][4], bh[4][2], bl[4][2];
            #pragma unroll
            for (int mi = 0; mi < 2; ++mi) {
                ldsm4(ah[mi], smem_u32(bAh + (a_row + mi * 16) * 40 + a_col + k16 * 16));
                ldsm4(al[mi], smem_u32(bAl + (a_row + mi * 16) * 40 + a_col + k16 * 16));
            }
            #pragma unroll
            for (int ni = 0; ni < 4; ++ni) {
                ldsm2(bh[ni], smem_u32(bBh + (b_row + ni * 8) * 40 + b_col + k16 * 16));
                ldsm2(bl[ni], smem_u32(bBl + (b_row + ni * 8) * 40 + b_col + k16 * 16));
            }
            #pragma unroll
            for (int mi = 0; mi < 2; ++mi) {
                #pragma unroll
                for (int ni = 0; ni < 4; ++ni) {
                    mma16816(acc[mi][ni], ah[mi], bh[ni]);
                    mma16816(acc[mi][ni], ah[mi], bl[ni]);
                    mma16816(acc[mi][ni], al[mi], bh[ni]);
                }
            }
        }
        if (kt + 1 < 16) {
            stash(buf ^ 1);
            __syncthreads();
            buf ^= 1;
        }
    }

    if (!is_p) {
        #pragma unroll
        for (int ni = 0; ni < 4; ++ni) {
            const int gn = n0 + wn * 32 + ni * 8 + (lane & 3) * 2;
            float2 cb = *(const float2*)(Cb + gn);
            float2 db = *(const float2*)(Db + gn);
            const float bxv = cb.x + db.x, byv = cb.y + db.y;
            #pragma unroll
            for (int mi = 0; mi < 2; ++mi) {
                const int gm = m0 + wm * 32 + mi * 16 + (lane >> 2);
                float2 o0 = {acc[mi][ni][0] + bxv, acc[mi][ni][1] + byv};
                float2 o1 = {acc[mi][ni][2] + bxv, acc[mi][ni][3] + byv};
                *(float2*)(Y + gm * 512 + gn) = o0;
                *(float2*)(Y + (gm + 8) * 512 + gn) = o1;
            }
        }
    } else if (wn < 2) {
        #pragma unroll
        for (int ni = 0; ni < 4; ++ni) {
            const int gn = wn * 32 + ni * 8 + (lane & 3) * 2;   // 0..63
            #pragma unroll
            for (int mi = 0; mi < 2; ++mi) {
                const int gm = m0 + wm * 32 + mi * 16 + (lane >> 2);
                float2 o0 = {acc[mi][ni][0], acc[mi][ni][1]};
                float2 o1 = {acc[mi][ni][2], acc[mi][ni][3]};
                *(float2*)(g_p + gm * 64 + gn) = o0;
                *(float2*)(g_p + (gm + 8) * 64 + gn) = o1;
            }
        }
    }
}

// ===========================================================================
// kernel_prep: 8x8 block-panel Gauss-Jordan (no pivot) + THREE Newton steps.
// 1024 threads. rho chain: 0.13 -> 1.7e-2 -> 2.9e-4 -> 8.4e-8.
// ===========================================================================
#define PREP_SMEM_FLOATS (64*132 + 8*132 + 64 + 512 + 64*68 + 64*68)

__global__ __launch_bounds__(1024, 1)
void kernel_prep(const float* __restrict__ A) {
    extern __shared__ float sm[];
    float* M      = sm;               // 64 x 132 augmented [A|I]
    float* sPanel = M + 64 * 132;     // 8 x 132
    float* sDinv  = sPanel + 8 * 132; // 8 x 8
    float* sC     = sDinv + 64;       // 64 x 8
    float* X      = sC + 512;         // 64 x 68
    float* T      = X + 64 * 68;      // 64 x 68
    const int tid = threadIdx.x;

    for (int e = tid; e < 4096; e += 1024) {
        int i = e >> 6, j = e & 63;
        M[i * 132 + j] = A[e];
        M[i * 132 + 64 + j] = (i == j) ? 1.0f : 0.0f;
    }
    __syncthreads();

    for (int p = 0; p < 8; ++p) {
        const int p8 = p * 8;
        if (tid < 512) {
            int i = tid >> 3, q = tid & 7;
            sC[tid] = M[i * 132 + p8 + q];
        }
        if (tid < 8) {
            float d[16];
            #pragma unroll
            for (int j = 0; j < 8; ++j) d[j] = M[(p8 + tid) * 132 + p8 + j];
            #pragma unroll
            for (int j = 0; j < 8; ++j) d[8 + j] = (tid == j) ? 1.0f : 0.0f;
            #pragma unroll
            for (int k = 0; k < 8; ++k) {
                float pv = __shfl_sync(0xFFu, d[k], k);
                float rcp = 1.0f / pv;
                float f = d[k] * rcp;
                #pragma unroll
                for (int j = 0; j < 16; ++j) {
                    float rkj = __shfl_sync(0xFFu, d[j], k);
                    d[j] = (tid == k) ? rkj * rcp : fmaf(-f, rkj, d[j]);
                }
            }
            #pragma unroll
            for (int j = 0; j < 8; ++j) sDinv[tid * 8 + j] = d[8 + j];
        }
        __syncthreads();
        {
            int r = tid >> 7, j = tid & 127;
            float acc = 0.0f;
            #pragma unroll
            for (int q = 0; q < 8; ++q)
                acc = fmaf(sDinv[r * 8 + q], M[(p8 + q) * 132 + j], acc);
            sPanel[r * 132 + j] = acc;
        }
        __syncthreads();
        {
            int i = tid >> 4, jq = (tid & 15) * 8;
            if (i >= p8 && i < p8 + 8) {
                int r = i - p8;
                *(float4*)&M[i * 132 + jq]     = *(const float4*)&sPanel[r * 132 + jq];
                *(float4*)&M[i * 132 + jq + 4] = *(const float4*)&sPanel[r * 132 + jq + 4];
            } else {
                float c[8];
                #pragma unroll
                for (int q = 0; q < 8; ++q) c[q] = sC[i * 8 + q];
                #pragma unroll
                for (int c4 = 0; c4 < 2; ++c4) {
                    float4 v = *(const float4*)&M[i * 132 + jq + c4 * 4];
                    #pragma unroll
                    for (int q = 0; q < 8; ++q) {
                        float4 pnl = *(const float4*)&sPanel[q * 132 + jq + c4 * 4];
                        v.x = fmaf(-c[q], pnl.x, v.x);
                        v.y = fmaf(-c[q], pnl.y, v.y);
                        v.z = fmaf(-c[q], pnl.z, v.z);
                        v.w = fmaf(-c[q], pnl.w, v.w);
                    }
                    *(float4*)&M[i * 132 + jq + c4 * 4] = v;
                }
            }
        }
        __syncthreads();
    }

    for (int e = tid; e < 4096; e += 1024) {
        int i = e >> 6, j = e & 63;
        X[i * 68 + j] = M[i * 132 + 64 + j];
    }
    __syncthreads();
    for (int e = tid; e < 4096; e += 1024) {
        int i = e >> 6, j = e & 63;
        M[i * 132 + j] = A[e];
    }
    __syncthreads();

    for (int it = 0; it < 3; ++it) {
        {
            int i = tid >> 4, j4 = (tid & 15) * 4;
            float4 acc;
            acc.x = (i == j4 + 0) ? 2.0f : 0.0f;
            acc.y = (i == j4 + 1) ? 2.0f : 0.0f;
            acc.z = (i == j4 + 2) ? 2.0f : 0.0f;
            acc.w = (i == j4 + 3) ? 2.0f : 0.0f;
            #pragma unroll 8
            for (int k2 = 0; k2 < 64; ++k2) {
                float a = M[i * 132 + k2];
                float4 xv = *(const float4*)&X[k2 * 68 + j4];
                acc.x = fmaf(-a, xv.x, acc.x);
                acc.y = fmaf(-a, xv.y, acc.y);
                acc.z = fmaf(-a, xv.z, acc.z);
                acc.w = fmaf(-a, xv.w, acc.w);
            }
            *(float4*)&T[i * 68 + j4] = acc;
        }
        __syncthreads();
        float4 r;
        {
            int i = tid >> 4, j4 = (tid & 15) * 4;
            float4 acc = {0.f, 0.f, 0.f, 0.f};
            #pragma unroll 8
            for (int k2 = 0; k2 < 64; ++k2) {
                float a = X[i * 68 + k2];
                float4 tv = *(const float4*)&T[k2 * 68 + j4];
                acc.x = fmaf(a, tv.x, acc.x);
                acc.y = fmaf(a, tv.y, acc.y);
                acc.z = fmaf(a, tv.z, acc.z);
                acc.w = fmaf(a, tv.w, acc.w);
            }
            r = acc;
        }
        __syncthreads();
        {
            int i = tid >> 4, j4 = (tid & 15) * 4;
            *(float4*)&X[i * 68 + j4] = r;
        }
        __syncthreads();
    }

    {
        int i = tid >> 4, j4 = (tid & 15) * 4;
        *(float4*)&g_Ainv[i * 64 + j4] = *(const float4*)&X[i * 68 + j4];
    }
}

// ===========================================================================
// kernel_scan: chunked selective scan, register-resident A slices.
// 256 blocks = chunks of 16 steps + 4-step warmup (truncation <= 2e-7).
// ===========================================================================
#define SCAN_STEPS_MAX 20
#define SCAN_SMEM_FLOATS (SCAN_STEPS_MAX*64 + SCAN_STEPS_MAX*64 + 4*SCAN_STEPS_MAX*64 + 64 + 256 + 64)

__global__ void kernel_scan(const float* __restrict__ A, const float* __restrict__ dlt) {
    extern __shared__ float sm[];
    float* sP     = sm;
    float* sV     = sP + SCAN_STEPS_MAX * 64;
    float* sPartV = sV + SCAN_STEPS_MAX * 64;
    float* sDelta = sPartV + 4 * SCAN_STEPS_MAX * 64;
    float* sPart  = sDelta + 64;
    float* sH     = sPart + 256;

    const int tid = threadIdx.x;
    const int g = blockIdx.x;
    const int lc = g & 127;
    const int warm = lc ? 4 : 0;
    const int t0g = g * 16 - warm;
    const int nsteps = 16 + warm;

    const float LOG2E = 1.4426950408889634f;
    const int n = tid & 63, q = tid >> 6;
    const int mb = q * 16;

    float aCol[16], aRow[16], aInv[16];
    #pragma unroll
    for (int i = 0; i < 16; ++i) {
        aCol[i] = LOG2E * A[(mb + i) * 64 + n];
    }
    #pragma unroll
    for (int i4 = 0; i4 < 4; ++i4) {
        float4 r = *(const float4*)(A + n * 64 + mb + i4 * 4);
        aRow[i4*4+0] = LOG2E * r.x; aRow[i4*4+1] = LOG2E * r.y;
        aRow[i4*4+2] = LOG2E * r.z; aRow[i4*4+3] = LOG2E * r.w;
        float4 iv = *(const float4*)(g_Ainv + n * 64 + mb + i4 * 4);
        aInv[i4*4+0] = iv.x; aInv[i4*4+1] = iv.y;
        aInv[i4*4+2] = iv.z; aInv[i4*4+3] = iv.w;
    }

    for (int e = tid; e < nsteps * 64; e += 256) {
        sP[e] = g_p[t0g * 64 + e];
    }
    if (tid < nsteps) sDelta[tid] = dlt[t0g + tid];
    if (tid < 64) sH[tid] = 0.0f;
    __syncthreads();

    for (int t = 0; t < nsteps; ++t) {
        float acc = 0.0f;
        #pragma unroll
        for (int i4 = 0; i4 < 4; ++i4) {
            float4 pv = *(const float4*)&sP[t * 64 + mb + i4 * 4];
            acc = fmaf(aInv[i4*4+0], pv.x, acc);
            acc = fmaf(aInv[i4*4+1], pv.y, acc);
            acc = fmaf(aInv[i4*4+2], pv.z, acc);
            acc = fmaf(aInv[i4*4+3], pv.w, acc);
        }
        sPartV[q * (SCAN_STEPS_MAX * 64) + t * 64 + n] = acc;
    }
    __syncthreads();
    for (int o = tid; o < nsteps * 64; o += 256) {
        sV[o] = sPartV[o] + sPartV[SCAN_STEPS_MAX*64 + o]
              + sPartV[2*SCAN_STEPS_MAX*64 + o] + sPartV[3*SCAN_STEPS_MAX*64 + o];
    }
    __syncthreads();

    for (int j = 0; j < nsteps; ++j) {
        const float dj = sDelta[j];
        float h[16], v[16];
        #pragma unroll
        for (int i4 = 0; i4 < 4; ++i4) {
            float4 hv = *(const float4*)&sH[mb + i4 * 4];
            h[i4*4+0] = hv.x; h[i4*4+1] = hv.y; h[i4*4+2] = hv.z; h[i4*4+3] = hv.w;
            float4 vv = *(const float4*)&sV[j * 64 + mb + i4 * 4];
            v[i4*4+0] = vv.x; v[i4*4+1] = vv.y; v[i4*4+2] = vv.z; v[i4*4+3] = vv.w;
        }
        float acc = 0.0f;
        #pragma unroll
        for (int i = 0; i < 16; ++i) {
            acc = fmaf(h[i], fast_exp2(dj * aCol[i]), acc);
            acc = fmaf(fast_exp2(dj * aRow[i]), v[i], acc);
        }
        sPart[q * 64 + n] = acc;
        __syncthreads();
        if (tid < 64) {
            float hn = sPart[tid] + sPart[64 + tid] + sPart[128 + tid] + sPart[192 + tid]
                       - sV[j * 64 + tid];
            sH[tid] = hn;
            if (j >= warm) g_hs[(t0g + j) * 64 + tid] = hn;
        }
        __syncthreads();
    }
}

// ===========================================================================
// kernel_y2: Y += hs @ C_w^T.  M=4096, N=512, K=64.
// ===========================================================================
__global__ void kernel_y2(const float* __restrict__ Cw, float* __restrict__ Y) {
    __shared__ float As[2][16][132];
    __shared__ float Bs[2][16][132];
    const int tid = threadIdx.x;
    const int m0 = blockIdx.y * 128;
    const int n0 = blockIdx.x * 128;

    const int r0 = tid >> 2;
    const int r1 = 64 + r0;
    const int kq = (tid & 3) * 4;

    const int w = tid >> 5, lane = tid & 31;
    const int wm = w & 3, wn = w >> 2;
    const int r = lane >> 3, c = lane & 7;
    const int aoff = wm * 32 + r * 8;
    const int boff0 = wn * 64 + c * 4;
    const int boff1 = boff0 + 32;

    float acc[8][8] = {};
    float4 pa0, pa1, pb0, pb1;

    auto fetch = [&](int kt) {
        int kk = kt * 16;
        pa0 = *(const float4*)(g_hs + (m0 + r0) * 64 + kk + kq);
        pa1 = *(const float4*)(g_hs + (m0 + r1) * 64 + kk + kq);
        pb0 = *(const float4*)(Cw + (n0 + r0) * 64 + kk + kq);
        pb1 = *(const float4*)(Cw + (n0 + r1) * 64 + kk + kq);
    };
    auto stash = [&](int b) {
        As[b][kq+0][r0] = pa0.x; As[b][kq+1][r0] = pa0.y;
        As[b][kq+2][r0] = pa0.z; As[b][kq+3][r0] = pa0.w;
        As[b][kq+0][r1] = pa1.x; As[b][kq+1][r1] = pa1.y;
        As[b][kq+2][r1] = pa1.z; As[b][kq+3][r1] = pa1.w;
        Bs[b][kq+0][r0] = pb0.x; Bs[b][kq+1][r0] = pb0.y;
        Bs[b][kq+2][r0] = pb0.z; Bs[b][kq+3][r0] = pb0.w;
        Bs[b][kq+0][r1] = pb1.x; Bs[b][kq+1][r1] = pb1.y;
        Bs[b][kq+2][r1] = pb1.z; Bs[b][kq+3][r1] = pb1.w;
    };

    fetch(0);
    stash(0);
    __syncthreads();

    int buf = 0;
    for (int kt = 0; kt < 4; ++kt) {
        if (kt + 1 < 4) fetch(kt + 1);
        #pragma unroll
        for (int k = 0; k < 16; ++k) {
            float4 a0 = *(const float4*)&As[buf][k][aoff];
            float4 a1 = *(const float4*)&As[buf][k][aoff + 4];
            float4 b0 = *(const float4*)&Bs[buf][k][boff0];
            float4 b1 = *(const float4*)&Bs[buf][k][boff1];
            float av[8] = {a0.x, a0.y, a0.z, a0.w, a1.x, a1.y, a1.z, a1.w};
            float bv[8] = {b0.x, b0.y, b0.z, b0.w, b1.x, b1.y, b1.z, b1.w};
            #pragma unroll
            for (int i = 0; i < 8; ++i) {
                #pragma unroll
                for (int jj = 0; jj < 8; ++jj) {
                    acc[i][jj] = fmaf(av[i], bv[jj], acc[i][jj]);
                }
            }
        }
        if (kt + 1 < 4) {
            stash(buf ^ 1);
            __syncthreads();
            buf ^= 1;
        }
    }

    const int cg0 = n0 + boff0;
    const int cg1 = n0 + boff1;
    #pragma unroll
    for (int i = 0; i < 8; ++i) {
        int gm = m0 + aoff + i;
        float4 y0 = *(const float4*)(Y + gm * 512 + cg0);
        float4 y1 = *(const float4*)(Y + gm * 512 + cg1);
        y0.x += acc[i][0]; y0.y += acc[i][1]; y0.z += acc[i][2]; y0.w += acc[i][3];
        y1.x += acc[i][4]; y1.y += acc[i][5]; y1.z += acc[i][6]; y1.w += acc[i][7];
        *(float4*)(Y + gm * 512 + cg0) = y0;
        *(float4*)(Y + gm * 512 + cg1) = y1;
    }
}

// ===========================================================================
struct LaunchCtx {
    cudaStream_t s1;
    cudaEvent_t e_root, e_prep;
    LaunchCtx() {
        cudaStreamCreateWithFlags(&s1, cudaStreamNonBlocking);
        cudaEventCreateWithFlags(&e_root, cudaEventDisableTiming);
        cudaEventCreateWithFlags(&e_prep, cudaEventDisableTiming);
    }
};

extern "C" void kernel_launch(void* const* d_in, const int* in_sizes, int n_in,
                              void* d_out, int out_size) {
    const float* x   = (const float*)d_in[0];   // (B,S,H)
    const float* dlt = (const float*)d_in[1];   // (B,S)
    const float* A   = (const float*)d_in[2];   // (N,N)
    const float* Bw  = (const float*)d_in[3];   // (N,H)
    const float* Cw  = (const float*)d_in[4];   // (H,N)
    const float* Cb  = (const float*)d_in[5];   // (H)
    const float* Dw  = (const float*)d_in[6];   // (H,H)
    const float* Db  = (const float*)d_in[7];   // (H)
    float* Y = (float*)d_out;

    static LaunchCtx ctx;

    const int prep_smem = PREP_SMEM_FLOATS * 4;
    const int scan_smem = SCAN_SMEM_FLOATS * 4;
    cudaFuncSetAttribute(kernel_prep, cudaFuncAttributeMaxDynamicSharedMemorySize, prep_smem);
    cudaFuncSetAttribute(kernel_scan, cudaFuncAttributeMaxDynamicSharedMemorySize, scan_smem);
    cudaFuncSetAttribute(kernel_y1p, cudaFuncAttributeMaxDynamicSharedMemorySize, Y1_SMEM_BYTES);

    // prep runs on s1 in parallel with y1p on the main stream.
    cudaEventRecord(ctx.e_root, 0);
    cudaStreamWaitEvent(ctx.s1, ctx.e_root, 0);
    kernel_prep<<<1, 1024, prep_smem, ctx.s1>>>(A);
    cudaEventRecord(ctx.e_prep, ctx.s1);

    kernel_y1p<<<dim3(5, 32), 512, Y1_SMEM_BYTES>>>(x, Dw, Bw, Cb, Db, Y);
    cudaStreamWaitEvent(0, ctx.e_prep, 0);         // scan needs Ainv (+ p from y1p)
    kernel_scan<<<256, 256, scan_smem>>>(A, dlt);
    kernel_y2<<<dim3(4, 32), 256>>>(Cw, Y);
}